// round 16
// baseline (speedup 1.0000x reference)
#include <cuda_runtime.h>
#include <cuda_bf16.h>

// ChronoRotationTransflormation: 6 inputs [B=8192, D=2048] fp32 ->
//   out[b] = ab / sqrt(aa*bb),
//   rot_r = hr*rr - hi*ri ; rot_i = -(hi*rr + hr*ri)
//   ab = sum(rot_r*tr + rot_i*ti); aa = sum(|rot|^2); bb = sum(tr^2+ti^2)
//
// FINAL (10x confirmed; best 57.82 us, 4/10 samples at the 57.8-57.9
// fast edge; best BW 6.98 TB/s). 512 thr/CTA, one row per CTA,
// 6 front-batched streaming LDG.128/thread (regs=32 -> exactly
// 4 CTAs/SM = full register file, ~91% occ), warp butterfly ->
// 16 smem partials -> one barrier -> warp-0 butterfly -> rsqrtf.
//
// Time floor = 402.65 MB irreducible reads / ~6.9 TB/s achieved chip
// memory throughput (6300 B/cyc path-independent LTS cap at the
// memory-bound DVFS clock). Measured-slower alternatives: warp-per-row
// (occ 23%), persistent grid (+regs, intra-CTA serialization),
// split-phase (+5.6 us second launch), 256-thr CTA. Model-rejected:
// LDG.256 / multi-row pipelining (cross the 32-reg full-RF boundary),
// TMA (same LTS cap), accumulator splitting (fma pipe at 10.7%).

#define D_DIM 2048
#define D4    (D_DIM / 4)      // 512 float4 per row
#define THREADS 512
#define NWARPS (THREADS / 32)  // 16

__global__ __launch_bounds__(THREADS, 4)
void chrono_rot_kernel(const float4* __restrict__ hr,
                       const float4* __restrict__ hi,
                       const float4* __restrict__ rr,
                       const float4* __restrict__ ri,
                       const float4* __restrict__ tr,
                       const float4* __restrict__ ti,
                       float* __restrict__ out)
{
    const int tid  = threadIdx.x;
    const int lane = tid & 31;
    const int wid  = tid >> 5;
    const size_t idx = (size_t)blockIdx.x * D4 + tid;

    // 6 independent streaming LDG.128, front-batched.
    const float4 HR = __ldcs(hr + idx);
    const float4 HI = __ldcs(hi + idx);
    const float4 RR = __ldcs(rr + idx);
    const float4 RI = __ldcs(ri + idx);
    const float4 TR = __ldcs(tr + idx);
    const float4 TI = __ldcs(ti + idx);

    float ab = 0.f, aa = 0.f, bb = 0.f;

    #pragma unroll
    for (int k = 0; k < 4; ++k) {
        const float hrk = (&HR.x)[k];
        const float hik = (&HI.x)[k];
        const float rrk = (&RR.x)[k];
        const float rik = (&RI.x)[k];
        const float trk = (&TR.x)[k];
        const float tik = (&TI.x)[k];

        const float rot_r = hrk * rrk - hik * rik;
        const float rot_i = -(hik * rrk + hrk * rik);

        ab = fmaf(rot_r, trk, fmaf(rot_i, tik, ab));
        aa = fmaf(rot_r, rot_r, fmaf(rot_i, rot_i, aa));
        bb = fmaf(trk, trk, fmaf(tik, tik, bb));
    }

    // Warp butterfly (3 independent chains, ILP-overlapped)
    #pragma unroll
    for (int off = 16; off > 0; off >>= 1) {
        ab += __shfl_xor_sync(0xFFFFFFFFu, ab, off);
        aa += __shfl_xor_sync(0xFFFFFFFFu, aa, off);
        bb += __shfl_xor_sync(0xFFFFFFFFu, bb, off);
    }

    __shared__ float s_ab[NWARPS];
    __shared__ float s_aa[NWARPS];
    __shared__ float s_bb[NWARPS];

    if (lane == 0) {
        s_ab[wid] = ab;
        s_aa[wid] = aa;
        s_bb[wid] = bb;
    }
    __syncthreads();

    if (wid == 0) {
        float vab = (lane < NWARPS) ? s_ab[lane] : 0.f;
        float vaa = (lane < NWARPS) ? s_aa[lane] : 0.f;
        float vbb = (lane < NWARPS) ? s_bb[lane] : 0.f;
        #pragma unroll
        for (int off = 8; off > 0; off >>= 1) {
            vab += __shfl_xor_sync(0xFFFFFFFFu, vab, off);
            vaa += __shfl_xor_sync(0xFFFFFFFFu, vaa, off);
            vbb += __shfl_xor_sync(0xFFFFFFFFu, vbb, off);
        }
        if (lane == 0) {
            out[blockIdx.x] = vab * rsqrtf(vaa * vbb);
        }
    }
}

extern "C" void kernel_launch(void* const* d_in, const int* in_sizes, int n_in,
                              void* d_out, int out_size)
{
    const float4* hr = (const float4*)d_in[0];
    const float4* hi = (const float4*)d_in[1];
    const float4* rr = (const float4*)d_in[2];
    const float4* ri = (const float4*)d_in[3];
    const float4* tr = (const float4*)d_in[4];
    const float4* ti = (const float4*)d_in[5];
    float* out = (float*)d_out;

    const int B = in_sizes[0] / D_DIM;   // 8192, one CTA per row
    chrono_rot_kernel<<<B, THREADS>>>(hr, hi, rr, ri, tr, ti, out);
}

// round 17
// speedup vs baseline: 1.0277x; 1.0277x over previous
#include <cuda_runtime.h>
#include <cuda_bf16.h>

// ChronoRotationTransflormation: 6 inputs [B=8192, D=2048] fp32 ->
//   out[b] = ab / sqrt(aa*bb),
//   rot_r = hr*rr - hi*ri ; rot_i = -(hi*rr + hr*ri)
//   ab = sum(rot_r*tr + rot_i*ti); aa = sum(|rot|^2); bb = sum(tr^2+ti^2)
//
// FINAL (11x confirmed; best 57.82 us; best BW 6.98 TB/s).
// 512 thr/CTA, one row per CTA, 6 front-batched streaming
// LDG.128/thread (regs=32 -> exactly 4 CTAs/SM = full register file,
// ~92% occ), warp butterfly -> 16 smem partials -> one barrier ->
// warp-0 butterfly -> rsqrtf.
//
// Time floor = 402.65 MB irreducible reads / ~6.9 TB/s achieved chip
// memory throughput (6300 B/cyc path-independent LTS cap at the
// memory-bound DVFS clock). Measured-slower alternatives: warp-per-row
// (occ 23%), persistent grid (+regs, intra-CTA serialization),
// split-phase (+5.6 us second launch), 256-thr CTA. Model-rejected:
// LDG.256 / multi-row pipelining (cross the 32-reg full-RF boundary),
// TMA (same LTS cap), accumulator splitting (fma pipe at 10.7%).

#define D_DIM 2048
#define D4    (D_DIM / 4)      // 512 float4 per row
#define THREADS 512
#define NWARPS (THREADS / 32)  // 16

__global__ __launch_bounds__(THREADS, 4)
void chrono_rot_kernel(const float4* __restrict__ hr,
                       const float4* __restrict__ hi,
                       const float4* __restrict__ rr,
                       const float4* __restrict__ ri,
                       const float4* __restrict__ tr,
                       const float4* __restrict__ ti,
                       float* __restrict__ out)
{
    const int tid  = threadIdx.x;
    const int lane = tid & 31;
    const int wid  = tid >> 5;
    const size_t idx = (size_t)blockIdx.x * D4 + tid;

    // 6 independent streaming LDG.128, front-batched.
    const float4 HR = __ldcs(hr + idx);
    const float4 HI = __ldcs(hi + idx);
    const float4 RR = __ldcs(rr + idx);
    const float4 RI = __ldcs(ri + idx);
    const float4 TR = __ldcs(tr + idx);
    const float4 TI = __ldcs(ti + idx);

    float ab = 0.f, aa = 0.f, bb = 0.f;

    #pragma unroll
    for (int k = 0; k < 4; ++k) {
        const float hrk = (&HR.x)[k];
        const float hik = (&HI.x)[k];
        const float rrk = (&RR.x)[k];
        const float rik = (&RI.x)[k];
        const float trk = (&TR.x)[k];
        const float tik = (&TI.x)[k];

        const float rot_r = hrk * rrk - hik * rik;
        const float rot_i = -(hik * rrk + hrk * rik);

        ab = fmaf(rot_r, trk, fmaf(rot_i, tik, ab));
        aa = fmaf(rot_r, rot_r, fmaf(rot_i, rot_i, aa));
        bb = fmaf(trk, trk, fmaf(tik, tik, bb));
    }

    // Warp butterfly (3 independent chains, ILP-overlapped)
    #pragma unroll
    for (int off = 16; off > 0; off >>= 1) {
        ab += __shfl_xor_sync(0xFFFFFFFFu, ab, off);
        aa += __shfl_xor_sync(0xFFFFFFFFu, aa, off);
        bb += __shfl_xor_sync(0xFFFFFFFFu, bb, off);
    }

    __shared__ float s_ab[NWARPS];
    __shared__ float s_aa[NWARPS];
    __shared__ float s_bb[NWARPS];

    if (lane == 0) {
        s_ab[wid] = ab;
        s_aa[wid] = aa;
        s_bb[wid] = bb;
    }
    __syncthreads();

    if (wid == 0) {
        float vab = (lane < NWARPS) ? s_ab[lane] : 0.f;
        float vaa = (lane < NWARPS) ? s_aa[lane] : 0.f;
        float vbb = (lane < NWARPS) ? s_bb[lane] : 0.f;
        #pragma unroll
        for (int off = 8; off > 0; off >>= 1) {
            vab += __shfl_xor_sync(0xFFFFFFFFu, vab, off);
            vaa += __shfl_xor_sync(0xFFFFFFFFu, vaa, off);
            vbb += __shfl_xor_sync(0xFFFFFFFFu, vbb, off);
        }
        if (lane == 0) {
            out[blockIdx.x] = vab * rsqrtf(vaa * vbb);
        }
    }
}

extern "C" void kernel_launch(void* const* d_in, const int* in_sizes, int n_in,
                              void* d_out, int out_size)
{
    const float4* hr = (const float4*)d_in[0];
    const float4* hi = (const float4*)d_in[1];
    const float4* rr = (const float4*)d_in[2];
    const float4* ri = (const float4*)d_in[3];
    const float4* tr = (const float4*)d_in[4];
    const float4* ti = (const float4*)d_in[5];
    float* out = (float*)d_out;

    const int B = in_sizes[0] / D_DIM;   // 8192, one CTA per row
    chrono_rot_kernel<<<B, THREADS>>>(hr, hi, rr, ri, tr, ti, out);
}